// round 13
// baseline (speedup 1.0000x reference)
#include <cuda_runtime.h>
#include <cuda_fp16.h>
#include <math.h>
#include <stdint.h>

#define D     128
#define NMAX  50000
#define EMAX  1600000
#define THREADS 256
#define BK2   64     // K per chunk (4 x k16 mma steps)
#define SAH   72     // A/B chunk smem stride in halves: (4g+tig)%32 bijective
#define SHH   136    // Hs smem stride in halves
#define ABUF_H (128 * SAH)   // 9216 halves = 18432 B
#define BBUF_H (128 * SAH)

// -------- device scratch --------
__device__ float  g_x[NMAX * D];       // fp32 x (epilogue math)
__device__ __half g_xh[NMAX * D];      // fp16 x (agg gather + gate A input)
__device__ __half g_xinh[NMAX * D];    // fp16 x_in
__device__ __half g_aggh[NMAX * D];    // fp16 agg
__device__ __half g_outh[NMAX * D];    // fp16 out
__device__ float  g_z[NMAX * D];       // fp32 z
__device__ __half g_rxh[NMAX * D];     // fp16 r*x
__device__ float  g_pz[NMAX * D];      // fp32 partial x@Wu2
__device__ float  g_pr[NMAX * D];      // fp32 partial x@Wr2
__device__ __half g_wh[10 * D * D];    // fp16 weights, TRANSPOSED [n][k]
__device__ int    g_cnt[NMAX];
__device__ int    g_start[NMAX + 1];
__device__ int    g_cur[NMAX];
__device__ int2   g_edges[EMAX];

__device__ __forceinline__ float sigf(float x) { return 1.0f / (1.0f + expf(-x)); }

__device__ __forceinline__ void mma_f16(float c[4],
                                        uint32_t a0, uint32_t a1, uint32_t a2, uint32_t a3,
                                        uint32_t b0, uint32_t b1) {
    asm volatile(
        "mma.sync.aligned.m16n8k16.row.col.f32.f16.f16.f32 "
        "{%0,%1,%2,%3}, {%4,%5,%6,%7}, {%8,%9}, {%0,%1,%2,%3};"
        : "+f"(c[0]), "+f"(c[1]), "+f"(c[2]), "+f"(c[3])
        : "r"(a0), "r"(a1), "r"(a2), "r"(a3), "r"(b0), "r"(b1));
}

// ---- cp.async helpers ----
__device__ __forceinline__ void cp16(void* dst_smem, const void* src, bool pred) {
    uint32_t dst = (uint32_t)__cvta_generic_to_shared(dst_smem);
    int sz = pred ? 16 : 0;
    asm volatile("cp.async.ca.shared.global [%0], [%1], 16, %2;\n"
                 :: "r"(dst), "l"(src), "r"(sz));
}
__device__ __forceinline__ void cp_commit() {
    asm volatile("cp.async.commit_group;\n");
}
template <int N>
__device__ __forceinline__ void cp_wait() {
    asm volatile("cp.async.wait_group %0;\n" :: "n"(N));
}

// A chunk [row0..+128) x [k0..+64) halves -> Abuf[row][k], stride SAH
__device__ __forceinline__ void cpA16(const __half* __restrict__ A, int row0, int Nrows,
                                      int k0, __half* Abuf, int tid) {
#pragma unroll
    for (int q2 = 0; q2 < 4; ++q2) {
        int idx = tid + q2 * 256;
        int row = idx >> 3;
        int q   = idx & 7;
        cp16(Abuf + row * SAH + q * 8,
             A + (size_t)(row0 + row) * D + k0 + q * 8,
             row0 + row < Nrows);
    }
}

// W chunk (transposed weights [n][k]) [0..128)n x [k0..+64) -> Bbuf[n][k]
__device__ __forceinline__ void cpB16(const __half* __restrict__ Wt, int k0,
                                      __half* Bbuf, int tid) {
#pragma unroll
    for (int q2 = 0; q2 < 4; ++q2) {
        int idx = tid + q2 * 256;
        int n = idx >> 3;
        int q = idx & 7;
        cp16(Bbuf + n * SAH + q * 8, Wt + (size_t)n * D + k0 + q * 8, true);
    }
}

// ---- mma over one 64-k chunk (4 x k16); A row-major stride sa, base k offset ak0 ----
__device__ __forceinline__ void mma_chunk16(const __half* Ar, int sa, int ak0,
                                            const __half* Bs,
                                            int m_base, int n_base, int g, int tig,
                                            float acc[2][8][4]) {
#pragma unroll
    for (int ks = 0; ks < 4; ++ks) {
        int ka = ak0 + ks * 16 + 2 * tig;
        int kb = ks * 16 + 2 * tig;
        uint32_t afr[2][4];
#pragma unroll
        for (int mt = 0; mt < 2; ++mt) {
            const __half* p0 = Ar + (m_base + mt * 16 + g) * sa + ka;
            const __half* p1 = p0 + 8 * sa;
            afr[mt][0] = *reinterpret_cast<const uint32_t*>(p0);
            afr[mt][1] = *reinterpret_cast<const uint32_t*>(p1);
            afr[mt][2] = *reinterpret_cast<const uint32_t*>(p0 + 8);
            afr[mt][3] = *reinterpret_cast<const uint32_t*>(p1 + 8);
        }
#pragma unroll
        for (int nt = 0; nt < 8; ++nt) {
            const __half* pb = Bs + (n_base + nt * 8 + g) * SAH + kb;
            uint32_t b0 = *reinterpret_cast<const uint32_t*>(pb);
            uint32_t b1 = *reinterpret_cast<const uint32_t*>(pb + 8);
            mma_f16(acc[0][nt], afr[0][0], afr[0][1], afr[0][2], afr[0][3], b0, b1);
            mma_f16(acc[1][nt], afr[1][0], afr[1][1], afr[1][2], afr[1][3], b0, b1);
        }
    }
}

// Single-source GEMM (K=128, 2 chunks of 64), 2-stage cp.async.
__device__ __forceinline__ void gemm1_h(const __half* A, const __half* Wt,
                                        __half* smA, __half* smB,
                                        int row0, int Nrows, int tid,
                                        int m_base, int n_base, int g, int tig,
                                        float acc[2][8][4]) {
    __half* Ab[2] = {smA, smA + ABUF_H};
    __half* Bb[2] = {smB, smB + BBUF_H};
    cpA16(A, row0, Nrows, 0, Ab[0], tid);
    cpB16(Wt, 0, Bb[0], tid);
    cp_commit();
#pragma unroll 1
    for (int t = 0; t < 2; ++t) {
        if (t < 1) {
            cpA16(A, row0, Nrows, BK2, Ab[1], tid);
            cpB16(Wt, BK2, Bb[1], tid);
            cp_commit();
            cp_wait<1>();
        } else {
            cp_wait<0>();
        }
        __syncthreads();
        mma_chunk16(Ab[t], SAH, 0, Bb[t], m_base, n_base, g, tig, acc);
        __syncthreads();
    }
}

// Dual-GEMM accumulate (4 chunks), 2-stage cp.async (R12-proven).
__device__ __forceinline__ void dual_gemm_h(const __half* A1, const __half* W1t,
                                            const __half* A2, const __half* W2t,
                                            __half* smA, __half* smB,
                                            int row0, int Nrows, int tid,
                                            int m_base, int n_base, int g, int tig,
                                            float acc[2][8][4]) {
    const __half* Aarr[2] = {A1, A2};
    const __half* Warr[2] = {W1t, W2t};
    __half* Ab[2] = {smA, smA + ABUF_H};
    __half* Bb[2] = {smB, smB + BBUF_H};

    cpA16(Aarr[0], row0, Nrows, 0, Ab[0], tid);
    cpB16(Warr[0], 0, Bb[0], tid);
    cp_commit();
#pragma unroll 1
    for (int t = 0; t < 4; ++t) {
        if (t < 3) {
            int tp = t + 1;
            cpA16(Aarr[tp >> 1], row0, Nrows, (tp & 1) * BK2, Ab[tp & 1], tid);
            cpB16(Warr[tp >> 1], (tp & 1) * BK2, Bb[tp & 1], tid);
            cp_commit();
            cp_wait<1>();
        } else {
            cp_wait<0>();
        }
        __syncthreads();
        mma_chunk16(Ab[t & 1], SAH, 0, Bb[t & 1], m_base, n_base, g, tig, acc);
        __syncthreads();
    }
}

// ===========================================================================
// Fused 2-layer MLP (R12-proven).
// ===========================================================================
template <bool DUAL>
__global__ void __launch_bounds__(THREADS, 2)
mlp2_mma_kernel(const __half* __restrict__ A,
                const __half* __restrict__ W1t, const float* __restrict__ b1,
                const __half* __restrict__ W2t, const float* __restrict__ b2,
                float* __restrict__ O, __half* __restrict__ OH, int Nrows)
{
    extern __shared__ __half smh[];
    __half* Ab[2] = {smh, smh + ABUF_H};
    __half* Bb[2] = {smh + 2 * ABUF_H, smh + 2 * ABUF_H + BBUF_H};
    __half* Hs = smh + 2 * ABUF_H + 2 * BBUF_H;

    int tid  = threadIdx.x;
    int warp = tid >> 5;
    int lane = tid & 31;
    int g    = lane >> 2;
    int tig  = lane & 3;
    int m_base = (warp >> 1) * 32;
    int n_base = (warp & 1) * 64;
    int row0 = blockIdx.x * 128;

    float acc[2][8][4];
#pragma unroll
    for (int mt = 0; mt < 2; ++mt)
#pragma unroll
        for (int nt = 0; nt < 8; ++nt)
#pragma unroll
            for (int i = 0; i < 4; ++i) acc[mt][nt][i] = 0.f;

    cpA16(A, row0, Nrows, 0, Ab[0], tid);
    cpB16(W1t, 0, Bb[0], tid);
    cp_commit();
#pragma unroll 1
    for (int kc = 0; kc < 2; ++kc) {
        if (kc < 1) {
            cpA16(A, row0, Nrows, BK2, Ab[1], tid);
            cpB16(W1t, BK2, Bb[1], tid);
            cp_commit();
            cp_wait<1>();
        } else {
            cp_wait<0>();
        }
        __syncthreads();
        mma_chunk16(Ab[kc & 1], SAH, 0, Bb[kc & 1], m_base, n_base, g, tig, acc);
        __syncthreads();
    }

    cpB16(W2t, 0, Bb[0], tid);
    cp_commit();

#pragma unroll
    for (int nt = 0; nt < 8; ++nt) {
        int col = n_base + nt * 8 + 2 * tig;
        float bx = __ldg(&b1[col]);
        float by = __ldg(&b1[col + 1]);
#pragma unroll
        for (int mt = 0; mt < 2; ++mt) {
#pragma unroll
            for (int h = 0; h < 2; ++h) {
                int row = m_base + mt * 16 + g + h * 8;
                float tx = fmaxf(acc[mt][nt][2 * h]     + bx, 0.f);
                float ty = fmaxf(acc[mt][nt][2 * h + 1] + by, 0.f);
                *reinterpret_cast<__half2*>(Hs + row * SHH + col) =
                    __float22half2_rn(make_float2(tx, ty));
                acc[mt][nt][2 * h] = 0.f;
                acc[mt][nt][2 * h + 1] = 0.f;
            }
        }
    }
    __syncthreads();

#pragma unroll 1
    for (int kc = 0; kc < 2; ++kc) {
        if (kc < 1) {
            cpB16(W2t, BK2, Bb[1], tid);
            cp_commit();
            cp_wait<1>();
        } else {
            cp_wait<0>();
        }
        __syncthreads();
        mma_chunk16(Hs, SHH, kc * BK2, Bb[kc & 1], m_base, n_base, g, tig, acc);
        __syncthreads();
    }

#pragma unroll
    for (int nt = 0; nt < 8; ++nt) {
        int col = n_base + nt * 8 + 2 * tig;
        float2 bb = make_float2(__ldg(&b2[col]), __ldg(&b2[col + 1]));
#pragma unroll
        for (int mt = 0; mt < 2; ++mt) {
#pragma unroll
            for (int h = 0; h < 2; ++h) {
                int row = row0 + m_base + mt * 16 + g + h * 8;
                if (row >= Nrows) continue;
                float vx = acc[mt][nt][2 * h]     + bb.x;
                float vy = acc[mt][nt][2 * h + 1] + bb.y;
                if (DUAL)
                    *reinterpret_cast<float2*>(&O[(size_t)row * D + col]) =
                        make_float2(vx, vy);
                *reinterpret_cast<__half2*>(&OH[(size_t)row * D + col]) =
                    __float22half2_rn(make_float2(vx, vy));
            }
        }
    }
}

// ===========================================================================
// xpart kernel (gridDim.y=2): P = x @ W{u2,r2} -> fp32 partials.
// Runs on side stream, overlapping the latency-bound agg kernel.
// ===========================================================================
__global__ void __launch_bounds__(THREADS, 2)
xpart_kernel(const __half* __restrict__ xh_, const __half* __restrict__ wh,
             float* __restrict__ Pz, float* __restrict__ Pr, int Nrows)
{
    __shared__ __half smA[2 * ABUF_H];
    __shared__ __half smB[2 * BBUF_H];

    int mode = blockIdx.y;
    const __half* W = wh + (size_t)(5 + 2 * mode) * D * D;  // Wu2 or Wr2
    float* P = mode ? Pr : Pz;

    int tid  = threadIdx.x;
    int warp = tid >> 5;
    int lane = tid & 31;
    int g    = lane >> 2;
    int tig  = lane & 3;
    int m_base = (warp >> 1) * 32;
    int n_base = (warp & 1) * 64;
    int row0 = blockIdx.x * 128;

    float acc[2][8][4];
#pragma unroll
    for (int mt = 0; mt < 2; ++mt)
#pragma unroll
        for (int nt = 0; nt < 8; ++nt)
#pragma unroll
            for (int i = 0; i < 4; ++i) acc[mt][nt][i] = 0.f;

    gemm1_h(xh_, W, smA, smB, row0, Nrows, tid, m_base, n_base, g, tig, acc);

#pragma unroll
    for (int nt = 0; nt < 8; ++nt) {
        int col = n_base + nt * 8 + 2 * tig;
#pragma unroll
        for (int mt = 0; mt < 2; ++mt) {
#pragma unroll
            for (int h = 0; h < 2; ++h) {
                int row = row0 + m_base + mt * 16 + g + h * 8;
                if (row >= Nrows) continue;
                size_t p = (size_t)row * 64 + (col >> 1);
                reinterpret_cast<float2*>(P)[p] =
                    make_float2(acc[mt][nt][2 * h], acc[mt][nt][2 * h + 1]);
            }
        }
    }
}

// ===========================================================================
// Merged z/r gate (gridDim.y=2): single GEMM out@W{u1,r1} + partial from P.
// ===========================================================================
__global__ void __launch_bounds__(THREADS, 2)
gate01_mma_kernel(const __half* __restrict__ out_, const __half* __restrict__ wh,
                  const float* __restrict__ Pz, const float* __restrict__ Pr,
                  const float* __restrict__ bu1, const float* __restrict__ bu2,
                  const float* __restrict__ br1, const float* __restrict__ br2,
                  int Nrows)
{
    __shared__ __half smA[2 * ABUF_H];
    __shared__ __half smB[2 * BBUF_H];

    int mode = blockIdx.y;
    const __half* Wa = wh + (size_t)(4 + 2 * mode) * D * D;  // Wu1 or Wr1
    const float* P = mode ? Pr : Pz;
    const float* ba = mode ? br1 : bu1;
    const float* bb_ = mode ? br2 : bu2;

    int tid  = threadIdx.x;
    int warp = tid >> 5;
    int lane = tid & 31;
    int g    = lane >> 2;
    int tig  = lane & 3;
    int m_base = (warp >> 1) * 32;
    int n_base = (warp & 1) * 64;
    int row0 = blockIdx.x * 128;

    float acc[2][8][4];
#pragma unroll
    for (int mt = 0; mt < 2; ++mt)
#pragma unroll
        for (int nt = 0; nt < 8; ++nt)
#pragma unroll
            for (int i = 0; i < 4; ++i) acc[mt][nt][i] = 0.f;

    gemm1_h(out_, Wa, smA, smB, row0, Nrows, tid, m_base, n_base, g, tig, acc);

    const float2* x2 = reinterpret_cast<const float2*>(g_x);
    const float2* P2 = reinterpret_cast<const float2*>(P);
#pragma unroll
    for (int nt = 0; nt < 8; ++nt) {
        int col = n_base + nt * 8 + 2 * tig;
        float2 bsum;
        bsum.x = __ldg(&ba[col])     + __ldg(&bb_[col]);
        bsum.y = __ldg(&ba[col + 1]) + __ldg(&bb_[col + 1]);
#pragma unroll
        for (int mt = 0; mt < 2; ++mt) {
#pragma unroll
            for (int h = 0; h < 2; ++h) {
                int row = row0 + m_base + mt * 16 + g + h * 8;
                if (row >= Nrows) continue;
                size_t p = (size_t)row * 64 + (col >> 1);
                float2 pv = P2[p];
                float sx = sigf(acc[mt][nt][2 * h]     + pv.x + bsum.x);
                float sy = sigf(acc[mt][nt][2 * h + 1] + pv.y + bsum.y);
                if (mode == 0) {
                    reinterpret_cast<float2*>(g_z)[p] = make_float2(sx, sy);
                } else {
                    float2 xv = x2[p];
                    *reinterpret_cast<__half2*>(&g_rxh[(size_t)row * D + col]) =
                        __float22half2_rn(make_float2(sx * xv.x, sy * xv.y));
                }
            }
        }
    }
}

// Final gate: O = (1-z)*x + z*tanh(out@Wo1 + rx@Wo2 + bo1 + bo2)
__global__ void __launch_bounds__(THREADS, 2)
gate2_mma_kernel(const __half* __restrict__ out_, const __half* __restrict__ rx_,
                 const __half* __restrict__ wh,
                 const float* __restrict__ bo1, const float* __restrict__ bo2,
                 float* __restrict__ O, int Nrows)
{
    __shared__ __half smA[2 * ABUF_H];
    __shared__ __half smB[2 * BBUF_H];

    const __half* Wa = wh + (size_t)8 * D * D;
    const __half* Wb = wh + (size_t)9 * D * D;

    int tid  = threadIdx.x;
    int warp = tid >> 5;
    int lane = tid & 31;
    int g    = lane >> 2;
    int tig  = lane & 3;
    int m_base = (warp >> 1) * 32;
    int n_base = (warp & 1) * 64;
    int row0 = blockIdx.x * 128;

    float acc[2][8][4];
#pragma unroll
    for (int mt = 0; mt < 2; ++mt)
#pragma unroll
        for (int nt = 0; nt < 8; ++nt)
#pragma unroll
            for (int i = 0; i < 4; ++i) acc[mt][nt][i] = 0.f;

    dual_gemm_h(out_, Wa, rx_, Wb, smA, smB, row0, Nrows, tid,
                m_base, n_base, g, tig, acc);

    const float2* x2 = reinterpret_cast<const float2*>(g_x);
    const float2* z2 = reinterpret_cast<const float2*>(g_z);
#pragma unroll
    for (int nt = 0; nt < 8; ++nt) {
        int col = n_base + nt * 8 + 2 * tig;
        float2 bsum;
        bsum.x = __ldg(&bo1[col])     + __ldg(&bo2[col]);
        bsum.y = __ldg(&bo1[col + 1]) + __ldg(&bo2[col + 1]);
#pragma unroll
        for (int mt = 0; mt < 2; ++mt) {
#pragma unroll
            for (int h = 0; h < 2; ++h) {
                int row = row0 + m_base + mt * 16 + g + h * 8;
                if (row >= Nrows) continue;
                float tx = acc[mt][nt][2 * h]     + bsum.x;
                float ty = acc[mt][nt][2 * h + 1] + bsum.y;
                size_t p = (size_t)row * 64 + (col >> 1);
                float2 xv = x2[p];
                float2 zv = z2[p];
                float2 o;
                o.x = (1.f - zv.x) * xv.x + zv.x * tanhf(tx);
                o.y = (1.f - zv.y) * xv.y + zv.y * tanhf(ty);
                reinterpret_cast<float2*>(O)[p] = o;
            }
        }
    }
}

// ===========================================================================
// Conversions
// ===========================================================================
__global__ void cvtw_kernel(const float* w0, const float* w1, const float* w2,
                            const float* w3, const float* w4, const float* w5,
                            const float* w6, const float* w7, const float* w8,
                            const float* w9, __half* dst)
{
    const float* ws[10] = {w0, w1, w2, w3, w4, w5, w6, w7, w8, w9};
    const float* w = ws[blockIdx.y];
    int i = blockIdx.x * 256 + threadIdx.x;
    int n = i >> 7;
    int k = i & 127;
    dst[(size_t)blockIdx.y * D * D + i] = __float2half_rn(w[(size_t)k * D + n]);
}

__global__ void cvtx_kernel(const float* __restrict__ src, __half* __restrict__ dst, int n4)
{
    int i = blockIdx.x * blockDim.x + threadIdx.x;
    if (i < n4) {
        float4 v = reinterpret_cast<const float4*>(src)[i];
        __half2 h0 = __float22half2_rn(make_float2(v.x, v.y));
        __half2 h1 = __float22half2_rn(make_float2(v.z, v.w));
        reinterpret_cast<uint2*>(dst)[i] = make_uint2(
            *reinterpret_cast<uint32_t*>(&h0), *reinterpret_cast<uint32_t*>(&h1));
    }
}

// ===========================================================================
// CSR build + atomic-free aggregation
// ===========================================================================
__global__ void zero_cnt_kernel(int Nn)
{
    int i = blockIdx.x * blockDim.x + threadIdx.x;
    if (i < Nn) g_cnt[i] = 0;
}

__global__ void count_kernel(const int* __restrict__ rows, int E)
{
    int e = blockIdx.x * blockDim.x + threadIdx.x;
    if (e < E) atomicAdd(&g_cnt[rows[e]], 1);
}

__global__ void scan_kernel(int Nn)
{
    __shared__ int warp_tot[32];
    int t = threadIdx.x;
    int lane = t & 31, w = t >> 5;
    int C = (Nn + 1023) / 1024;
    int lo = t * C;
    int hi = min(lo + C, Nn);

    int sum = 0;
    for (int i = lo; i < hi; ++i) sum += g_cnt[i];

    int v = sum;
#pragma unroll
    for (int o = 1; o < 32; o <<= 1) {
        int u = __shfl_up_sync(0xffffffffu, v, o);
        if (lane >= o) v += u;
    }
    if (lane == 31) warp_tot[w] = v;
    __syncthreads();
    if (w == 0) {
        int tv = warp_tot[lane];
#pragma unroll
        for (int o = 1; o < 32; o <<= 1) {
            int u = __shfl_up_sync(0xffffffffu, tv, o);
            if (lane >= o) tv += u;
        }
        warp_tot[lane] = tv;
    }
    __syncthreads();
    int incl = v + (w > 0 ? warp_tot[w - 1] : 0);
    int run = incl - sum;

    for (int i = lo; i < hi; ++i) {
        int c = g_cnt[i];
        g_start[i] = run;
        g_cur[i] = run;
        run += c;
    }
    if (t == 1023) g_start[Nn] = run;
}

__global__ void fill_kernel(const int* __restrict__ rows, const int* __restrict__ cols,
                            const float* __restrict__ vals, int E)
{
    int e = blockIdx.x * blockDim.x + threadIdx.x;
    if (e < E) {
        int r = rows[e];
        int pos = atomicAdd(&g_cur[r], 1);
        g_edges[pos] = make_int2(cols[e], __float_as_int(vals[e]));
    }
}

// Warp per node; fp16 gather; 8 edges in flight; fp16 output.
__global__ void agg_kernel(const __half* __restrict__ xh, __half* __restrict__ aggh, int Nn)
{
    int gw = (blockIdx.x * blockDim.x + threadIdx.x) >> 5;
    int lane = threadIdx.x & 31;
    if (gw >= Nn) return;

    int s = __ldg(&g_start[gw]);
    int t = __ldg(&g_start[gw + 1]);
    const uint2* x2 = reinterpret_cast<const uint2*>(xh);

    float4 acc = make_float4(0.f, 0.f, 0.f, 0.f);
    int j = s;
    for (; j + 8 <= t; j += 8) {
        int2 ee[8];
        uint2 uu[8];
#pragma unroll
        for (int q = 0; q < 8; ++q) ee[q] = __ldg(&g_edges[j + q]);
#pragma unroll
        for (int q = 0; q < 8; ++q) uu[q] = x2[(size_t)ee[q].x * 32 + lane];
#pragma unroll
        for (int q = 0; q < 8; ++q) {
            float v = __int_as_float(ee[q].y);
            float2 a = __half22float2(*reinterpret_cast<__half2*>(&uu[q].x));
            float2 b = __half22float2(*reinterpret_cast<__half2*>(&uu[q].y));
            acc.x += v * a.x; acc.y += v * a.y; acc.z += v * b.x; acc.w += v * b.y;
        }
    }
    for (; j < t; ++j) {
        int2 ea = __ldg(&g_edges[j]);
        uint2 ua = x2[(size_t)ea.x * 32 + lane];
        float va = __int_as_float(ea.y);
        float2 a = __half22float2(*reinterpret_cast<__half2*>(&ua.x));
        float2 b = __half22float2(*reinterpret_cast<__half2*>(&ua.y));
        acc.x += va * a.x; acc.y += va * a.y; acc.z += va * b.x; acc.w += va * b.y;
    }
    __half2 h0 = __float22half2_rn(make_float2(acc.x, acc.y));
    __half2 h1 = __float22half2_rn(make_float2(acc.z, acc.w));
    reinterpret_cast<uint2*>(aggh)[(size_t)gw * 32 + lane] = make_uint2(
        *reinterpret_cast<uint32_t*>(&h0), *reinterpret_cast<uint32_t*>(&h1));
}

// ---------------------------------------------------------------------------
extern "C" void kernel_launch(void* const* d_in, const int* in_sizes, int n_in,
                              void* d_out, int out_size)
{
    const float* x_in  = (const float*)d_in[0];
    const int*   rows  = (const int*)  d_in[1];
    const int*   cols  = (const int*)  d_in[2];
    const float* vals  = (const float*)d_in[3];
    const float* m1_W1 = (const float*)d_in[4];
    const float* m1_b1 = (const float*)d_in[5];
    const float* m1_W2 = (const float*)d_in[6];
    const float* m1_b2 = (const float*)d_in[7];
    const float* m2_W1 = (const float*)d_in[8];
    const float* m2_b1 = (const float*)d_in[9];
    const float* m2_W2 = (const float*)d_in[10];
    const float* m2_b2 = (const float*)d_in[11];
    const float* Wu1   = (const float*)d_in[12];
    const float* bu1   = (const float*)d_in[13];
    const float* Wu2   = (const float*)d_in[14];
    const float* bu2   = (const float*)d_in[15];
    const float* Wr1   = (const float*)d_in[16];
    const float* br1   = (const float*)d_in[17];
    const float* Wr2   = (const float*)d_in[18];
    const float* br2   = (const float*)d_in[19];
    const float* Wo1   = (const float*)d_in[20];
    const float* bo1   = (const float*)d_in[21];
    const float* Wo2   = (const float*)d_in[22];
    const float* bo2   = (const float*)d_in[23];

    int N = in_sizes[0] / D;
    int E = in_sizes[1];

    float *px, *ppz, *ppr;
    __half *pxh, *pxinh, *paggh, *pouth, *prxh, *pwh;
    cudaGetSymbolAddress((void**)&px,    g_x);
    cudaGetSymbolAddress((void**)&ppz,   g_pz);
    cudaGetSymbolAddress((void**)&ppr,   g_pr);
    cudaGetSymbolAddress((void**)&pxh,   g_xh);
    cudaGetSymbolAddress((void**)&pxinh, g_xinh);
    cudaGetSymbolAddress((void**)&paggh, g_aggh);
    cudaGetSymbolAddress((void**)&pouth, g_outh);
    cudaGetSymbolAddress((void**)&prxh,  g_rxh);
    cudaGetSymbolAddress((void**)&pwh,   g_wh);

    static cudaStream_t s_side = nullptr;
    static cudaEvent_t ev_fork = nullptr, ev_join = nullptr, ev_x = nullptr, ev_xp = nullptr;
    if (!s_side) {
        cudaStreamCreateWithFlags(&s_side, cudaStreamNonBlocking);
        cudaEventCreateWithFlags(&ev_fork, cudaEventDisableTiming);
        cudaEventCreateWithFlags(&ev_join, cudaEventDisableTiming);
        cudaEventCreateWithFlags(&ev_x,    cudaEventDisableTiming);
        cudaEventCreateWithFlags(&ev_xp,   cudaEventDisableTiming);
    }

    int smem_mlp = (2 * ABUF_H + 2 * BBUF_H + 128 * SHH) * (int)sizeof(__half);
    cudaFuncSetAttribute(mlp2_mma_kernel<true>,  cudaFuncAttributeMaxDynamicSharedMemorySize, smem_mlp);
    cudaFuncSetAttribute(mlp2_mma_kernel<false>, cudaFuncAttributeMaxDynamicSharedMemorySize, smem_mlp);

    int nblk = (N + 127) / 128;
    int eblk = (E + 255) / 256;
    int n4 = N * D / 4;

    // ---- fork: CSR build on side stream ----
    cudaEventRecord(ev_fork, 0);
    cudaStreamWaitEvent(s_side, ev_fork, 0);
    zero_cnt_kernel<<<(N + 255) / 256, 256, 0, s_side>>>(N);
    count_kernel<<<eblk, 256, 0, s_side>>>(rows, E);
    scan_kernel<<<1, 1024, 0, s_side>>>(N);
    fill_kernel<<<eblk, 256, 0, s_side>>>(rows, cols, vals, E);
    cudaEventRecord(ev_join, s_side);

    // ---- main: conversions + mlp1 ----
    dim3 wgrid(64, 10);
    cvtw_kernel<<<wgrid, 256>>>(m1_W1, m1_W2, m2_W1, m2_W2, Wu1, Wu2, Wr1, Wr2, Wo1, Wo2, pwh);
    cvtx_kernel<<<(n4 + 255) / 256, 256>>>(x_in, pxinh, n4);

    mlp2_mma_kernel<true><<<nblk, THREADS, smem_mlp>>>(
        pxinh, pwh + 0 * D * D, m1_b1, pwh + 1 * D * D, m1_b2, px, pxh, N);
    cudaEventRecord(ev_x, 0);

    // ---- side: xpart (x@Wu2, x@Wr2) overlaps agg ----
    cudaStreamWaitEvent(s_side, ev_x, 0);
    dim3 gridxp(nblk, 2);
    xpart_kernel<<<gridxp, THREADS, 0, s_side>>>(pxh, pwh, ppz, ppr, N);
    cudaEventRecord(ev_xp, s_side);

    // ---- main: agg, mlp2 ----
    cudaStreamWaitEvent(0, ev_join, 0);
    agg_kernel<<<(N * 32 + 255) / 256, 256>>>(pxh, paggh, N);
    mlp2_mma_kernel<false><<<nblk, THREADS, smem_mlp>>>(
        paggh, pwh + 2 * D * D, m2_b1, pwh + 3 * D * D, m2_b2, nullptr, pouth, N);

    // ---- gates ----
    cudaStreamWaitEvent(0, ev_xp, 0);
    dim3 grid01(nblk, 2);
    gate01_mma_kernel<<<grid01, THREADS>>>(pouth, pwh, ppz, ppr, bu1, bu2, br1, br2, N);
    gate2_mma_kernel<<<nblk, THREADS>>>(pouth, prxh, pwh, bo1, bo2, (float*)d_out, N);
}

// round 14
// speedup vs baseline: 1.0917x; 1.0917x over previous
#include <cuda_runtime.h>
#include <cuda_fp16.h>
#include <math.h>
#include <stdint.h>

#define D     128
#define NMAX  50000
#define EMAX  1600000
#define THREADS 256
#define BK2   64     // K per chunk (4 x k16 mma steps)
#define SAH   72     // A/B chunk smem stride in halves: (4g+tig)%32 bijective
#define SHH   136    // Hs smem stride in halves
#define ABUF_H (128 * SAH)   // 9216 halves = 18432 B
#define BBUF_H (128 * SAH)

// -------- device scratch --------
__device__ float  g_x[NMAX * D];       // fp32 x (epilogue math)
__device__ __half g_xh[NMAX * D];      // fp16 x (agg gather + gate A input)
__device__ __half g_xinh[NMAX * D];    // fp16 x_in
__device__ __half g_aggh[NMAX * D];    // fp16 agg
__device__ __half g_outh[NMAX * D];    // fp16 out
__device__ float  g_z[NMAX * D];       // fp32 z
__device__ __half g_rxh[NMAX * D];     // fp16 r*x
__device__ __half g_wh[10 * D * D];    // fp16 weights, TRANSPOSED [n][k]
__device__ int    g_cnt[NMAX];
__device__ int    g_start[NMAX + 1];
__device__ int    g_cur[NMAX];
__device__ int2   g_edges[EMAX];

__device__ __forceinline__ float sigf(float x) { return 1.0f / (1.0f + expf(-x)); }

__device__ __forceinline__ void mma_f16(float c[4],
                                        uint32_t a0, uint32_t a1, uint32_t a2, uint32_t a3,
                                        uint32_t b0, uint32_t b1) {
    asm volatile(
        "mma.sync.aligned.m16n8k16.row.col.f32.f16.f16.f32 "
        "{%0,%1,%2,%3}, {%4,%5,%6,%7}, {%8,%9}, {%0,%1,%2,%3};"
        : "+f"(c[0]), "+f"(c[1]), "+f"(c[2]), "+f"(c[3])
        : "r"(a0), "r"(a1), "r"(a2), "r"(a3), "r"(b0), "r"(b1));
}

// ---- cp.async helpers ----
__device__ __forceinline__ void cp16(void* dst_smem, const void* src, bool pred) {
    uint32_t dst = (uint32_t)__cvta_generic_to_shared(dst_smem);
    int sz = pred ? 16 : 0;
    asm volatile("cp.async.ca.shared.global [%0], [%1], 16, %2;\n"
                 :: "r"(dst), "l"(src), "r"(sz));
}
__device__ __forceinline__ void cp_commit() {
    asm volatile("cp.async.commit_group;\n");
}
template <int N>
__device__ __forceinline__ void cp_wait() {
    asm volatile("cp.async.wait_group %0;\n" :: "n"(N));
}

// A chunk [row0..+128) x [k0..+64) halves -> Abuf[row][k], stride SAH
__device__ __forceinline__ void cpA16(const __half* __restrict__ A, int row0, int Nrows,
                                      int k0, __half* Abuf, int tid) {
#pragma unroll
    for (int q2 = 0; q2 < 4; ++q2) {
        int idx = tid + q2 * 256;
        int row = idx >> 3;
        int q   = idx & 7;
        cp16(Abuf + row * SAH + q * 8,
             A + (size_t)(row0 + row) * D + k0 + q * 8,
             row0 + row < Nrows);
    }
}

// W chunk (transposed weights [n][k]) [0..128)n x [k0..+64) -> Bbuf[n][k]
__device__ __forceinline__ void cpB16(const __half* __restrict__ Wt, int k0,
                                      __half* Bbuf, int tid) {
#pragma unroll
    for (int q2 = 0; q2 < 4; ++q2) {
        int idx = tid + q2 * 256;
        int n = idx >> 3;
        int q = idx & 7;
        cp16(Bbuf + n * SAH + q * 8, Wt + (size_t)n * D + k0 + q * 8, true);
    }
}

// ---- mma over one 64-k chunk (4 x k16); A row-major stride sa, base k offset ak0 ----
__device__ __forceinline__ void mma_chunk16(const __half* Ar, int sa, int ak0,
                                            const __half* Bs,
                                            int m_base, int n_base, int g, int tig,
                                            float acc[2][8][4]) {
#pragma unroll
    for (int ks = 0; ks < 4; ++ks) {
        int ka = ak0 + ks * 16 + 2 * tig;
        int kb = ks * 16 + 2 * tig;
        uint32_t afr[2][4];
#pragma unroll
        for (int mt = 0; mt < 2; ++mt) {
            const __half* p0 = Ar + (m_base + mt * 16 + g) * sa + ka;
            const __half* p1 = p0 + 8 * sa;
            afr[mt][0] = *reinterpret_cast<const uint32_t*>(p0);
            afr[mt][1] = *reinterpret_cast<const uint32_t*>(p1);
            afr[mt][2] = *reinterpret_cast<const uint32_t*>(p0 + 8);
            afr[mt][3] = *reinterpret_cast<const uint32_t*>(p1 + 8);
        }
#pragma unroll
        for (int nt = 0; nt < 8; ++nt) {
            const __half* pb = Bs + (n_base + nt * 8 + g) * SAH + kb;
            uint32_t b0 = *reinterpret_cast<const uint32_t*>(pb);
            uint32_t b1 = *reinterpret_cast<const uint32_t*>(pb + 8);
            mma_f16(acc[0][nt], afr[0][0], afr[0][1], afr[0][2], afr[0][3], b0, b1);
            mma_f16(acc[1][nt], afr[1][0], afr[1][1], afr[1][2], afr[1][3], b0, b1);
        }
    }
}

// Dual-GEMM accumulate (4 chunks of 64 k), 2-stage cp.async (R12-proven).
__device__ __forceinline__ void dual_gemm_h(const __half* A1, const __half* W1t,
                                            const __half* A2, const __half* W2t,
                                            __half* smA, __half* smB,
                                            int row0, int Nrows, int tid,
                                            int m_base, int n_base, int g, int tig,
                                            float acc[2][8][4]) {
    const __half* Aarr[2] = {A1, A2};
    const __half* Warr[2] = {W1t, W2t};
    __half* Ab[2] = {smA, smA + ABUF_H};
    __half* Bb[2] = {smB, smB + BBUF_H};

    cpA16(Aarr[0], row0, Nrows, 0, Ab[0], tid);
    cpB16(Warr[0], 0, Bb[0], tid);
    cp_commit();
#pragma unroll 1
    for (int t = 0; t < 4; ++t) {
        if (t < 3) {
            int tp = t + 1;
            cpA16(Aarr[tp >> 1], row0, Nrows, (tp & 1) * BK2, Ab[tp & 1], tid);
            cpB16(Warr[tp >> 1], (tp & 1) * BK2, Bb[tp & 1], tid);
            cp_commit();
            cp_wait<1>();
        } else {
            cp_wait<0>();
        }
        __syncthreads();
        mma_chunk16(Ab[t & 1], SAH, 0, Bb[t & 1], m_base, n_base, g, tig, acc);
        __syncthreads();
    }
}

// ===========================================================================
// Fused 2-layer MLP (R12-proven).
// ===========================================================================
template <bool DUAL>
__global__ void __launch_bounds__(THREADS, 2)
mlp2_mma_kernel(const __half* __restrict__ A,
                const __half* __restrict__ W1t, const float* __restrict__ b1,
                const __half* __restrict__ W2t, const float* __restrict__ b2,
                float* __restrict__ O, __half* __restrict__ OH, int Nrows)
{
    extern __shared__ __half smh[];
    __half* Ab[2] = {smh, smh + ABUF_H};
    __half* Bb[2] = {smh + 2 * ABUF_H, smh + 2 * ABUF_H + BBUF_H};
    __half* Hs = smh + 2 * ABUF_H + 2 * BBUF_H;

    int tid  = threadIdx.x;
    int warp = tid >> 5;
    int lane = tid & 31;
    int g    = lane >> 2;
    int tig  = lane & 3;
    int m_base = (warp >> 1) * 32;
    int n_base = (warp & 1) * 64;
    int row0 = blockIdx.x * 128;

    float acc[2][8][4];
#pragma unroll
    for (int mt = 0; mt < 2; ++mt)
#pragma unroll
        for (int nt = 0; nt < 8; ++nt)
#pragma unroll
            for (int i = 0; i < 4; ++i) acc[mt][nt][i] = 0.f;

    cpA16(A, row0, Nrows, 0, Ab[0], tid);
    cpB16(W1t, 0, Bb[0], tid);
    cp_commit();
#pragma unroll 1
    for (int kc = 0; kc < 2; ++kc) {
        if (kc < 1) {
            cpA16(A, row0, Nrows, BK2, Ab[1], tid);
            cpB16(W1t, BK2, Bb[1], tid);
            cp_commit();
            cp_wait<1>();
        } else {
            cp_wait<0>();
        }
        __syncthreads();
        mma_chunk16(Ab[kc & 1], SAH, 0, Bb[kc & 1], m_base, n_base, g, tig, acc);
        __syncthreads();
    }

    cpB16(W2t, 0, Bb[0], tid);
    cp_commit();

#pragma unroll
    for (int nt = 0; nt < 8; ++nt) {
        int col = n_base + nt * 8 + 2 * tig;
        float bx = __ldg(&b1[col]);
        float by = __ldg(&b1[col + 1]);
#pragma unroll
        for (int mt = 0; mt < 2; ++mt) {
#pragma unroll
            for (int h = 0; h < 2; ++h) {
                int row = m_base + mt * 16 + g + h * 8;
                float tx = fmaxf(acc[mt][nt][2 * h]     + bx, 0.f);
                float ty = fmaxf(acc[mt][nt][2 * h + 1] + by, 0.f);
                *reinterpret_cast<__half2*>(Hs + row * SHH + col) =
                    __float22half2_rn(make_float2(tx, ty));
                acc[mt][nt][2 * h] = 0.f;
                acc[mt][nt][2 * h + 1] = 0.f;
            }
        }
    }
    __syncthreads();

#pragma unroll 1
    for (int kc = 0; kc < 2; ++kc) {
        if (kc < 1) {
            cpB16(W2t, BK2, Bb[1], tid);
            cp_commit();
            cp_wait<1>();
        } else {
            cp_wait<0>();
        }
        __syncthreads();
        mma_chunk16(Hs, SHH, kc * BK2, Bb[kc & 1], m_base, n_base, g, tig, acc);
        __syncthreads();
    }

#pragma unroll
    for (int nt = 0; nt < 8; ++nt) {
        int col = n_base + nt * 8 + 2 * tig;
        float2 bb = make_float2(__ldg(&b2[col]), __ldg(&b2[col + 1]));
#pragma unroll
        for (int mt = 0; mt < 2; ++mt) {
#pragma unroll
            for (int h = 0; h < 2; ++h) {
                int row = row0 + m_base + mt * 16 + g + h * 8;
                if (row >= Nrows) continue;
                float vx = acc[mt][nt][2 * h]     + bb.x;
                float vy = acc[mt][nt][2 * h + 1] + bb.y;
                if (DUAL)
                    *reinterpret_cast<float2*>(&O[(size_t)row * D + col]) =
                        make_float2(vx, vy);
                *reinterpret_cast<__half2*>(&OH[(size_t)row * D + col]) =
                    __float22half2_rn(make_float2(vx, vy));
            }
        }
    }
}

// ===========================================================================
// Merged z/r gate kernel (gridDim.y = 2), fp16 GEMMs (R12-proven).
// ===========================================================================
__global__ void __launch_bounds__(THREADS, 2)
gate01_mma_kernel(const __half* __restrict__ out_, const __half* __restrict__ xh_,
                  const __half* __restrict__ wh,
                  const float* __restrict__ bu1, const float* __restrict__ bu2,
                  const float* __restrict__ br1, const float* __restrict__ br2,
                  int Nrows)
{
    __shared__ __half smA[2 * ABUF_H];
    __shared__ __half smB[2 * BBUF_H];

    int mode = blockIdx.y;
    const __half* Wa = wh + (size_t)(4 + 2 * mode) * D * D;
    const __half* Wb = wh + (size_t)(5 + 2 * mode) * D * D;
    const float* ba = mode ? br1 : bu1;
    const float* bb_ = mode ? br2 : bu2;

    int tid  = threadIdx.x;
    int warp = tid >> 5;
    int lane = tid & 31;
    int g    = lane >> 2;
    int tig  = lane & 3;
    int m_base = (warp >> 1) * 32;
    int n_base = (warp & 1) * 64;
    int row0 = blockIdx.x * 128;

    float acc[2][8][4];
#pragma unroll
    for (int mt = 0; mt < 2; ++mt)
#pragma unroll
        for (int nt = 0; nt < 8; ++nt)
#pragma unroll
            for (int i = 0; i < 4; ++i) acc[mt][nt][i] = 0.f;

    dual_gemm_h(out_, Wa, xh_, Wb, smA, smB, row0, Nrows, tid,
                m_base, n_base, g, tig, acc);

    const float2* x2 = reinterpret_cast<const float2*>(g_x);
#pragma unroll
    for (int nt = 0; nt < 8; ++nt) {
        int col = n_base + nt * 8 + 2 * tig;
        float2 bsum;
        bsum.x = __ldg(&ba[col])     + __ldg(&bb_[col]);
        bsum.y = __ldg(&ba[col + 1]) + __ldg(&bb_[col + 1]);
#pragma unroll
        for (int mt = 0; mt < 2; ++mt) {
#pragma unroll
            for (int h = 0; h < 2; ++h) {
                int row = row0 + m_base + mt * 16 + g + h * 8;
                if (row >= Nrows) continue;
                float sx = sigf(acc[mt][nt][2 * h]     + bsum.x);
                float sy = sigf(acc[mt][nt][2 * h + 1] + bsum.y);
                size_t p = (size_t)row * 64 + (col >> 1);
                if (mode == 0) {
                    reinterpret_cast<float2*>(g_z)[p] = make_float2(sx, sy);
                } else {
                    float2 xv = x2[p];
                    *reinterpret_cast<__half2*>(&g_rxh[(size_t)row * D + col]) =
                        __float22half2_rn(make_float2(sx * xv.x, sy * xv.y));
                }
            }
        }
    }
}

// Final gate: O = (1-z)*x + z*tanh(out@Wo1 + rx@Wo2 + bo1 + bo2)
__global__ void __launch_bounds__(THREADS, 2)
gate2_mma_kernel(const __half* __restrict__ out_, const __half* __restrict__ rx_,
                 const __half* __restrict__ wh,
                 const float* __restrict__ bo1, const float* __restrict__ bo2,
                 float* __restrict__ O, int Nrows)
{
    __shared__ __half smA[2 * ABUF_H];
    __shared__ __half smB[2 * BBUF_H];

    const __half* Wa = wh + (size_t)8 * D * D;
    const __half* Wb = wh + (size_t)9 * D * D;

    int tid  = threadIdx.x;
    int warp = tid >> 5;
    int lane = tid & 31;
    int g    = lane >> 2;
    int tig  = lane & 3;
    int m_base = (warp >> 1) * 32;
    int n_base = (warp & 1) * 64;
    int row0 = blockIdx.x * 128;

    float acc[2][8][4];
#pragma unroll
    for (int mt = 0; mt < 2; ++mt)
#pragma unroll
        for (int nt = 0; nt < 8; ++nt)
#pragma unroll
            for (int i = 0; i < 4; ++i) acc[mt][nt][i] = 0.f;

    dual_gemm_h(out_, Wa, rx_, Wb, smA, smB, row0, Nrows, tid,
                m_base, n_base, g, tig, acc);

    const float2* x2 = reinterpret_cast<const float2*>(g_x);
    const float2* z2 = reinterpret_cast<const float2*>(g_z);
#pragma unroll
    for (int nt = 0; nt < 8; ++nt) {
        int col = n_base + nt * 8 + 2 * tig;
        float2 bsum;
        bsum.x = __ldg(&bo1[col])     + __ldg(&bo2[col]);
        bsum.y = __ldg(&bo1[col + 1]) + __ldg(&bo2[col + 1]);
#pragma unroll
        for (int mt = 0; mt < 2; ++mt) {
#pragma unroll
            for (int h = 0; h < 2; ++h) {
                int row = row0 + m_base + mt * 16 + g + h * 8;
                if (row >= Nrows) continue;
                float tx = acc[mt][nt][2 * h]     + bsum.x;
                float ty = acc[mt][nt][2 * h + 1] + bsum.y;
                size_t p = (size_t)row * 64 + (col >> 1);
                float2 xv = x2[p];
                float2 zv = z2[p];
                float2 o;
                o.x = (1.f - zv.x) * xv.x + zv.x * tanhf(tx);
                o.y = (1.f - zv.y) * xv.y + zv.y * tanhf(ty);
                reinterpret_cast<float2*>(O)[p] = o;
            }
        }
    }
}

// ===========================================================================
// Conversions
// ===========================================================================
__global__ void cvtw_kernel(const float* w0, const float* w1, const float* w2,
                            const float* w3, const float* w4, const float* w5,
                            const float* w6, const float* w7, const float* w8,
                            const float* w9, __half* dst)
{
    const float* ws[10] = {w0, w1, w2, w3, w4, w5, w6, w7, w8, w9};
    const float* w = ws[blockIdx.y];
    int i = blockIdx.x * 256 + threadIdx.x;
    int n = i >> 7;
    int k = i & 127;
    dst[(size_t)blockIdx.y * D * D + i] = __float2half_rn(w[(size_t)k * D + n]);
}

__global__ void cvtx_kernel(const float* __restrict__ src, __half* __restrict__ dst, int n4)
{
    int i = blockIdx.x * blockDim.x + threadIdx.x;
    if (i < n4) {
        float4 v = reinterpret_cast<const float4*>(src)[i];
        __half2 h0 = __float22half2_rn(make_float2(v.x, v.y));
        __half2 h1 = __float22half2_rn(make_float2(v.z, v.w));
        reinterpret_cast<uint2*>(dst)[i] = make_uint2(
            *reinterpret_cast<uint32_t*>(&h0), *reinterpret_cast<uint32_t*>(&h1));
    }
}

// ===========================================================================
// CSR build + atomic-free aggregation
// ===========================================================================
__global__ void zero_cnt_kernel(int Nn)
{
    int i = blockIdx.x * blockDim.x + threadIdx.x;
    if (i < Nn) g_cnt[i] = 0;
}

__global__ void count_kernel(const int* __restrict__ rows, int E)
{
    int e = blockIdx.x * blockDim.x + threadIdx.x;
    if (e < E) atomicAdd(&g_cnt[rows[e]], 1);
}

__global__ void scan_kernel(int Nn)
{
    __shared__ int warp_tot[32];
    int t = threadIdx.x;
    int lane = t & 31, w = t >> 5;
    int C = (Nn + 1023) / 1024;
    int lo = t * C;
    int hi = min(lo + C, Nn);

    int sum = 0;
    for (int i = lo; i < hi; ++i) sum += g_cnt[i];

    int v = sum;
#pragma unroll
    for (int o = 1; o < 32; o <<= 1) {
        int u = __shfl_up_sync(0xffffffffu, v, o);
        if (lane >= o) v += u;
    }
    if (lane == 31) warp_tot[w] = v;
    __syncthreads();
    if (w == 0) {
        int tv = warp_tot[lane];
#pragma unroll
        for (int o = 1; o < 32; o <<= 1) {
            int u = __shfl_up_sync(0xffffffffu, tv, o);
            if (lane >= o) tv += u;
        }
        warp_tot[lane] = tv;
    }
    __syncthreads();
    int incl = v + (w > 0 ? warp_tot[w - 1] : 0);
    int run = incl - sum;

    for (int i = lo; i < hi; ++i) {
        int c = g_cnt[i];
        g_start[i] = run;
        g_cur[i] = run;
        run += c;
    }
    if (t == 1023) g_start[Nn] = run;
}

__global__ void fill_kernel(const int* __restrict__ rows, const int* __restrict__ cols,
                            const float* __restrict__ vals, int E)
{
    int e = blockIdx.x * blockDim.x + threadIdx.x;
    if (e < E) {
        int r = rows[e];
        int pos = atomicAdd(&g_cur[r], 1);
        g_edges[pos] = make_int2(cols[e], __float_as_int(vals[e]));
    }
}

// ===========================================================================
// agg: warp per node, HALF-WARP PER EDGE (16B loads).
// lanes 0-15 handle even edges, 16-31 odd edges; each lane loads uint4
// (8 halves = features seg*8..seg*8+7). Final shfl_xor(16) combine.
// 2x bytes in flight and half the LDG count vs R12.
// ===========================================================================
__global__ void agg_kernel(const __half* __restrict__ xh, __half* __restrict__ aggh, int Nn)
{
    int gw = (blockIdx.x * blockDim.x + threadIdx.x) >> 5;
    int lane = threadIdx.x & 31;
    if (gw >= Nn) return;
    int seg  = lane & 15;
    int epos = lane >> 4;

    int s = __ldg(&g_start[gw]);
    int t = __ldg(&g_start[gw + 1]);
    const uint4* x4 = reinterpret_cast<const uint4*>(xh);   // 16 uint4 per row

    float acc[8];
#pragma unroll
    for (int i = 0; i < 8; ++i) acc[i] = 0.f;

    for (int j = s; j < t; j += 8) {
        int   cc[4];
        float vv[4];
        uint4 uu[4];
#pragma unroll
        for (int q = 0; q < 4; ++q) {
            int e = j + 2 * q + epos;
            bool ok = (e < t);
            int2 ed = ok ? __ldg(&g_edges[e]) : make_int2(0, 0);
            cc[q] = ed.x;
            vv[q] = ok ? __int_as_float(ed.y) : 0.f;
        }
#pragma unroll
        for (int q = 0; q < 4; ++q)
            uu[q] = x4[(size_t)cc[q] * 16 + seg];
#pragma unroll
        for (int q = 0; q < 4; ++q) {
            float v = vv[q];
            const __half2* h = reinterpret_cast<const __half2*>(&uu[q]);
#pragma unroll
            for (int p = 0; p < 4; ++p) {
                float2 f = __half22float2(h[p]);
                acc[2 * p]     += v * f.x;
                acc[2 * p + 1] += v * f.y;
            }
        }
    }

#pragma unroll
    for (int i = 0; i < 8; ++i)
        acc[i] += __shfl_xor_sync(0xffffffffu, acc[i], 16);

    if (lane < 16) {
        __half2 hh[4];
#pragma unroll
        for (int p = 0; p < 4; ++p)
            hh[p] = __float22half2_rn(make_float2(acc[2 * p], acc[2 * p + 1]));
        reinterpret_cast<uint4*>(aggh)[(size_t)gw * 16 + seg] =
            *reinterpret_cast<uint4*>(hh);
    }
}

// ---------------------------------------------------------------------------
extern "C" void kernel_launch(void* const* d_in, const int* in_sizes, int n_in,
                              void* d_out, int out_size)
{
    const float* x_in  = (const float*)d_in[0];
    const int*   rows  = (const int*)  d_in[1];
    const int*   cols  = (const int*)  d_in[2];
    const float* vals  = (const float*)d_in[3];
    const float* m1_W1 = (const float*)d_in[4];
    const float* m1_b1 = (const float*)d_in[5];
    const float* m1_W2 = (const float*)d_in[6];
    const float* m1_b2 = (const float*)d_in[7];
    const float* m2_W1 = (const float*)d_in[8];
    const float* m2_b1 = (const float*)d_in[9];
    const float* m2_W2 = (const float*)d_in[10];
    const float* m2_b2 = (const float*)d_in[11];
    const float* Wu1   = (const float*)d_in[12];
    const float* bu1   = (const float*)d_in[13];
    const float* Wu2   = (const float*)d_in[14];
    const float* bu2   = (const float*)d_in[15];
    const float* Wr1   = (const float*)d_in[16];
    const float* br1   = (const float*)d_in[17];
    const float* Wr2   = (const float*)d_in[18];
    const float* br2   = (const float*)d_in[19];
    const float* Wo1   = (const float*)d_in[20];
    const float* bo1   = (const float*)d_in[21];
    const float* Wo2   = (const float*)d_in[22];
    const float* bo2   = (const float*)d_in[23];

    int N = in_sizes[0] / D;
    int E = in_sizes[1];

    float *px;
    __half *pxh, *pxinh, *paggh, *pouth, *prxh, *pwh;
    cudaGetSymbolAddress((void**)&px,    g_x);
    cudaGetSymbolAddress((void**)&pxh,   g_xh);
    cudaGetSymbolAddress((void**)&pxinh, g_xinh);
    cudaGetSymbolAddress((void**)&paggh, g_aggh);
    cudaGetSymbolAddress((void**)&pouth, g_outh);
    cudaGetSymbolAddress((void**)&prxh,  g_rxh);
    cudaGetSymbolAddress((void**)&pwh,   g_wh);

    static cudaStream_t s_side = nullptr;
    static cudaEvent_t ev_fork = nullptr, ev_join = nullptr;
    if (!s_side) {
        cudaStreamCreateWithFlags(&s_side, cudaStreamNonBlocking);
        cudaEventCreateWithFlags(&ev_fork, cudaEventDisableTiming);
        cudaEventCreateWithFlags(&ev_join, cudaEventDisableTiming);
    }

    int smem_mlp = (2 * ABUF_H + 2 * BBUF_H + 128 * SHH) * (int)sizeof(__half);  // 108544 B
    cudaFuncSetAttribute(mlp2_mma_kernel<true>,  cudaFuncAttributeMaxDynamicSharedMemorySize, smem_mlp);
    cudaFuncSetAttribute(mlp2_mma_kernel<false>, cudaFuncAttributeMaxDynamicSharedMemorySize, smem_mlp);

    int nblk = (N + 127) / 128;
    int eblk = (E + 255) / 256;
    int n4 = N * D / 4;

    // ---- fork: CSR build on side stream ----
    cudaEventRecord(ev_fork, 0);
    cudaStreamWaitEvent(s_side, ev_fork, 0);
    zero_cnt_kernel<<<(N + 255) / 256, 256, 0, s_side>>>(N);
    count_kernel<<<eblk, 256, 0, s_side>>>(rows, E);
    scan_kernel<<<1, 1024, 0, s_side>>>(N);
    fill_kernel<<<eblk, 256, 0, s_side>>>(rows, cols, vals, E);
    cudaEventRecord(ev_join, s_side);

    // ---- main: conversions, then pipeline ----
    dim3 wgrid(64, 10);
    cvtw_kernel<<<wgrid, 256>>>(m1_W1, m1_W2, m2_W1, m2_W2, Wu1, Wu2, Wr1, Wr2, Wo1, Wo2, pwh);
    cvtx_kernel<<<(n4 + 255) / 256, 256>>>(x_in, pxinh, n4);

    mlp2_mma_kernel<true><<<nblk, THREADS, smem_mlp>>>(
        pxinh, pwh + 0 * D * D, m1_b1, pwh + 1 * D * D, m1_b2, px, pxh, N);

    cudaStreamWaitEvent(0, ev_join, 0);
    agg_kernel<<<(N * 32 + 255) / 256, 256>>>(pxh, paggh, N);

    mlp2_mma_kernel<false><<<nblk, THREADS, smem_mlp>>>(
        paggh, pwh + 2 * D * D, m2_b1, pwh + 3 * D * D, m2_b2, nullptr, pouth, N);

    dim3 grid01(nblk, 2);
    gate01_mma_kernel<<<grid01, THREADS>>>(pouth, pxh, pwh, bu1, bu2, br1, br2, N);
    gate2_mma_kernel<<<nblk, THREADS>>>(pouth, prxh, pwh, bo1, bo2, (float*)d_out, N);
}

// round 15
// speedup vs baseline: 1.0923x; 1.0006x over previous
#include <cuda_runtime.h>
#include <cuda_fp16.h>
#include <math.h>
#include <stdint.h>

#define D     128
#define NMAX  50000
#define EMAX  1600000
#define THREADS 256
#define BK2   64     // K per chunk (4 x k16 mma steps)
#define SAH   72     // A/B chunk smem stride in halves: (4g+tig)%32 bijective
#define SHH   136    // Hs smem stride in halves
#define ABUF_H  (128 * SAH)   // 9216 halves (128-row A tile / B tile)
#define ABUF64_H (64 * SAH)   // 4608 halves (64-row A tile)
#define BBUF_H  (128 * SAH)

// -------- device scratch --------
__device__ float  g_x[NMAX * D];
__device__ __half g_xh[NMAX * D];
__device__ __half g_xinh[NMAX * D];
__device__ __half g_aggh[NMAX * D];
__device__ __half g_outh[NMAX * D];
__device__ float  g_z[NMAX * D];
__device__ __half g_rxh[NMAX * D];
__device__ __half g_wh[10 * D * D];   // fp16 weights, TRANSPOSED [n][k]
__device__ int    g_cnt[NMAX];
__device__ int    g_start[NMAX + 1];
__device__ int    g_cur[NMAX];
__device__ int2   g_edges[EMAX];

__device__ __forceinline__ float sigf(float x) { return 1.0f / (1.0f + expf(-x)); }

__device__ __forceinline__ void mma_f16(float c[4],
                                        uint32_t a0, uint32_t a1, uint32_t a2, uint32_t a3,
                                        uint32_t b0, uint32_t b1) {
    asm volatile(
        "mma.sync.aligned.m16n8k16.row.col.f32.f16.f16.f32 "
        "{%0,%1,%2,%3}, {%4,%5,%6,%7}, {%8,%9}, {%0,%1,%2,%3};"
        : "+f"(c[0]), "+f"(c[1]), "+f"(c[2]), "+f"(c[3])
        : "r"(a0), "r"(a1), "r"(a2), "r"(a3), "r"(b0), "r"(b1));
}

// ---- cp.async helpers ----
__device__ __forceinline__ void cp16(void* dst_smem, const void* src, bool pred) {
    uint32_t dst = (uint32_t)__cvta_generic_to_shared(dst_smem);
    int sz = pred ? 16 : 0;
    asm volatile("cp.async.ca.shared.global [%0], [%1], 16, %2;\n"
                 :: "r"(dst), "l"(src), "r"(sz));
}
__device__ __forceinline__ void cp_commit() {
    asm volatile("cp.async.commit_group;\n");
}
template <int N>
__device__ __forceinline__ void cp_wait() {
    asm volatile("cp.async.wait_group %0;\n" :: "n"(N));
}

// A chunk [row0..+128) x [k0..+64) -> Abuf[row][k], stride SAH (128-row tiles)
__device__ __forceinline__ void cpA16(const __half* __restrict__ A, int row0, int Nrows,
                                      int k0, __half* Abuf, int tid) {
#pragma unroll
    for (int q2 = 0; q2 < 4; ++q2) {
        int idx = tid + q2 * 256;
        int row = idx >> 3;
        int q   = idx & 7;
        cp16(Abuf + row * SAH + q * 8,
             A + (size_t)(row0 + row) * D + k0 + q * 8,
             row0 + row < Nrows);
    }
}

// A chunk [row0..+64) x [k0..+64) -> Abuf[row][k] (64-row tiles)
__device__ __forceinline__ void cpA64(const __half* __restrict__ A, int row0, int Nrows,
                                      int k0, __half* Abuf, int tid) {
#pragma unroll
    for (int q2 = 0; q2 < 2; ++q2) {
        int idx = tid + q2 * 256;      // 0..511
        int row = idx >> 3;            // 0..63
        int q   = idx & 7;
        cp16(Abuf + row * SAH + q * 8,
             A + (size_t)(row0 + row) * D + k0 + q * 8,
             row0 + row < Nrows);
    }
}

// W chunk (transposed weights [n][k]) [0..128)n x [k0..+64) -> Bbuf[n][k]
__device__ __forceinline__ void cpB16(const __half* __restrict__ Wt, int k0,
                                      __half* Bbuf, int tid) {
#pragma unroll
    for (int q2 = 0; q2 < 4; ++q2) {
        int idx = tid + q2 * 256;
        int n = idx >> 3;
        int q = idx & 7;
        cp16(Bbuf + n * SAH + q * 8, Wt + (size_t)n * D + k0 + q * 8, true);
    }
}

// ---- mma over one 64-k chunk (4 x k16); NT n-tiles; A row-major stride sa ----
template <int NT>
__device__ __forceinline__ void mma_chunk16(const __half* Ar, int sa, int ak0,
                                            const __half* Bs,
                                            int m_base, int n_base, int g, int tig,
                                            float acc[2][NT][4]) {
#pragma unroll
    for (int ks = 0; ks < 4; ++ks) {
        int ka = ak0 + ks * 16 + 2 * tig;
        int kb = ks * 16 + 2 * tig;
        uint32_t afr[2][4];
#pragma unroll
        for (int mt = 0; mt < 2; ++mt) {
            const __half* p0 = Ar + (m_base + mt * 16 + g) * sa + ka;
            const __half* p1 = p0 + 8 * sa;
            afr[mt][0] = *reinterpret_cast<const uint32_t*>(p0);
            afr[mt][1] = *reinterpret_cast<const uint32_t*>(p1);
            afr[mt][2] = *reinterpret_cast<const uint32_t*>(p0 + 8);
            afr[mt][3] = *reinterpret_cast<const uint32_t*>(p1 + 8);
        }
#pragma unroll
        for (int nt = 0; nt < NT; ++nt) {
            const __half* pb = Bs + (n_base + nt * 8 + g) * SAH + kb;
            uint32_t b0 = *reinterpret_cast<const uint32_t*>(pb);
            uint32_t b1 = *reinterpret_cast<const uint32_t*>(pb + 8);
            mma_f16(acc[0][nt], afr[0][0], afr[0][1], afr[0][2], afr[0][3], b0, b1);
            mma_f16(acc[1][nt], afr[1][0], afr[1][1], afr[1][2], afr[1][3], b0, b1);
        }
    }
}

// Dual-GEMM, 128-row tiles, NT=8 (R12-proven; used by gate01).
__device__ __forceinline__ void dual_gemm_h(const __half* A1, const __half* W1t,
                                            const __half* A2, const __half* W2t,
                                            __half* smA, __half* smB,
                                            int row0, int Nrows, int tid,
                                            int m_base, int n_base, int g, int tig,
                                            float acc[2][8][4]) {
    const __half* Aarr[2] = {A1, A2};
    const __half* Warr[2] = {W1t, W2t};
    __half* Ab[2] = {smA, smA + ABUF_H};
    __half* Bb[2] = {smB, smB + BBUF_H};

    cpA16(Aarr[0], row0, Nrows, 0, Ab[0], tid);
    cpB16(Warr[0], 0, Bb[0], tid);
    cp_commit();
#pragma unroll 1
    for (int t = 0; t < 4; ++t) {
        if (t < 3) {
            int tp = t + 1;
            cpA16(Aarr[tp >> 1], row0, Nrows, (tp & 1) * BK2, Ab[tp & 1], tid);
            cpB16(Warr[tp >> 1], (tp & 1) * BK2, Bb[tp & 1], tid);
            cp_commit();
            cp_wait<1>();
        } else {
            cp_wait<0>();
        }
        __syncthreads();
        mma_chunk16<8>(Ab[t & 1], SAH, 0, Bb[t & 1], m_base, n_base, g, tig, acc);
        __syncthreads();
    }
}

// Dual-GEMM, 64-row tiles, NT=4 (used by gate2).
__device__ __forceinline__ void dual_gemm_h64(const __half* A1, const __half* W1t,
                                              const __half* A2, const __half* W2t,
                                              __half* smA, __half* smB,
                                              int row0, int Nrows, int tid,
                                              int m_base, int n_base, int g, int tig,
                                              float acc[2][4][4]) {
    const __half* Aarr[2] = {A1, A2};
    const __half* Warr[2] = {W1t, W2t};
    __half* Ab[2] = {smA, smA + ABUF64_H};
    __half* Bb[2] = {smB, smB + BBUF_H};

    cpA64(Aarr[0], row0, Nrows, 0, Ab[0], tid);
    cpB16(Warr[0], 0, Bb[0], tid);
    cp_commit();
#pragma unroll 1
    for (int t = 0; t < 4; ++t) {
        if (t < 3) {
            int tp = t + 1;
            cpA64(Aarr[tp >> 1], row0, Nrows, (tp & 1) * BK2, Ab[tp & 1], tid);
            cpB16(Warr[tp >> 1], (tp & 1) * BK2, Bb[tp & 1], tid);
            cp_commit();
            cp_wait<1>();
        } else {
            cp_wait<0>();
        }
        __syncthreads();
        mma_chunk16<4>(Ab[t & 1], SAH, 0, Bb[t & 1], m_base, n_base, g, tig, acc);
        __syncthreads();
    }
}

// ===========================================================================
// Fused 2-layer MLP, 64-ROW blocks (782 blocks -> 88% wave util).
// Warp grid 2(M) x 4(N); warp tile 32x32; acc[2][4][4].
// ===========================================================================
template <bool DUAL>
__global__ void __launch_bounds__(THREADS, 2)
mlp2_mma_kernel(const __half* __restrict__ A,
                const __half* __restrict__ W1t, const float* __restrict__ b1,
                const __half* __restrict__ W2t, const float* __restrict__ b2,
                float* __restrict__ O, __half* __restrict__ OH, int Nrows)
{
    extern __shared__ __half smh[];
    __half* Ab[2] = {smh, smh + ABUF64_H};
    __half* Bb[2] = {smh + 2 * ABUF64_H, smh + 2 * ABUF64_H + BBUF_H};
    __half* Hs = smh + 2 * ABUF64_H + 2 * BBUF_H;   // 64*SHH halves

    int tid  = threadIdx.x;
    int warp = tid >> 5;
    int lane = tid & 31;
    int g    = lane >> 2;
    int tig  = lane & 3;
    int m_base = (warp >> 2) * 32;   // 0,32
    int n_base = (warp & 3) * 32;    // 0,32,64,96
    int row0 = blockIdx.x * 64;

    float acc[2][4][4];
#pragma unroll
    for (int mt = 0; mt < 2; ++mt)
#pragma unroll
        for (int nt = 0; nt < 4; ++nt)
#pragma unroll
            for (int i = 0; i < 4; ++i) acc[mt][nt][i] = 0.f;

    // ---- layer 1: A @ W1 (2 chunks) ----
    cpA64(A, row0, Nrows, 0, Ab[0], tid);
    cpB16(W1t, 0, Bb[0], tid);
    cp_commit();
#pragma unroll 1
    for (int kc = 0; kc < 2; ++kc) {
        if (kc < 1) {
            cpA64(A, row0, Nrows, BK2, Ab[1], tid);
            cpB16(W1t, BK2, Bb[1], tid);
            cp_commit();
            cp_wait<1>();
        } else {
            cp_wait<0>();
        }
        __syncthreads();
        mma_chunk16<4>(Ab[kc & 1], SAH, 0, Bb[kc & 1], m_base, n_base, g, tig, acc);
        __syncthreads();
    }

    cpB16(W2t, 0, Bb[0], tid);
    cp_commit();

    // ---- epilogue 1: relu(acc + b1) -> Hs[row][col] fp16 ----
#pragma unroll
    for (int nt = 0; nt < 4; ++nt) {
        int col = n_base + nt * 8 + 2 * tig;
        float bx = __ldg(&b1[col]);
        float by = __ldg(&b1[col + 1]);
#pragma unroll
        for (int mt = 0; mt < 2; ++mt) {
#pragma unroll
            for (int h = 0; h < 2; ++h) {
                int row = m_base + mt * 16 + g + h * 8;
                float tx = fmaxf(acc[mt][nt][2 * h]     + bx, 0.f);
                float ty = fmaxf(acc[mt][nt][2 * h + 1] + by, 0.f);
                *reinterpret_cast<__half2*>(Hs + row * SHH + col) =
                    __float22half2_rn(make_float2(tx, ty));
                acc[mt][nt][2 * h] = 0.f;
                acc[mt][nt][2 * h + 1] = 0.f;
            }
        }
    }
    __syncthreads();

    // ---- layer 2: Hs @ W2 (2 chunks) ----
#pragma unroll 1
    for (int kc = 0; kc < 2; ++kc) {
        if (kc < 1) {
            cpB16(W2t, BK2, Bb[1], tid);
            cp_commit();
            cp_wait<1>();
        } else {
            cp_wait<0>();
        }
        __syncthreads();
        mma_chunk16<4>(Hs, SHH, kc * BK2, Bb[kc & 1], m_base, n_base, g, tig, acc);
        __syncthreads();
    }

    // ---- epilogue 2 ----
#pragma unroll
    for (int nt = 0; nt < 4; ++nt) {
        int col = n_base + nt * 8 + 2 * tig;
        float2 bb = make_float2(__ldg(&b2[col]), __ldg(&b2[col + 1]));
#pragma unroll
        for (int mt = 0; mt < 2; ++mt) {
#pragma unroll
            for (int h = 0; h < 2; ++h) {
                int row = row0 + m_base + mt * 16 + g + h * 8;
                if (row >= Nrows) continue;
                float vx = acc[mt][nt][2 * h]     + bb.x;
                float vy = acc[mt][nt][2 * h + 1] + bb.y;
                if (DUAL)
                    *reinterpret_cast<float2*>(&O[(size_t)row * D + col]) =
                        make_float2(vx, vy);
                *reinterpret_cast<__half2*>(&OH[(size_t)row * D + col]) =
                    __float22half2_rn(make_float2(vx, vy));
            }
        }
    }
}

// ===========================================================================
// Merged z/r gate kernel (gridDim.y = 2), 128-row tiles (R12-proven).
// ===========================================================================
__global__ void __launch_bounds__(THREADS, 2)
gate01_mma_kernel(const __half* __restrict__ out_, const __half* __restrict__ xh_,
                  const __half* __restrict__ wh,
                  const float* __restrict__ bu1, const float* __restrict__ bu2,
                  const float* __restrict__ br1, const float* __restrict__ br2,
                  int Nrows)
{
    __shared__ __half smA[2 * ABUF_H];
    __shared__ __half smB[2 * BBUF_H];

    int mode = blockIdx.y;
    const __half* Wa = wh + (size_t)(4 + 2 * mode) * D * D;
    const __half* Wb = wh + (size_t)(5 + 2 * mode) * D * D;
    const float* ba = mode ? br1 : bu1;
    const float* bb_ = mode ? br2 : bu2;

    int tid  = threadIdx.x;
    int warp = tid >> 5;
    int lane = tid & 31;
    int g    = lane >> 2;
    int tig  = lane & 3;
    int m_base = (warp >> 1) * 32;
    int n_base = (warp & 1) * 64;
    int row0 = blockIdx.x * 128;

    float acc[2][8][4];
#pragma unroll
    for (int mt = 0; mt < 2; ++mt)
#pragma unroll
        for (int nt = 0; nt < 8; ++nt)
#pragma unroll
            for (int i = 0; i < 4; ++i) acc[mt][nt][i] = 0.f;

    dual_gemm_h(out_, Wa, xh_, Wb, smA, smB, row0, Nrows, tid,
                m_base, n_base, g, tig, acc);

    const float2* x2 = reinterpret_cast<const float2*>(g_x);
#pragma unroll
    for (int nt = 0; nt < 8; ++nt) {
        int col = n_base + nt * 8 + 2 * tig;
        float2 bsum;
        bsum.x = __ldg(&ba[col])     + __ldg(&bb_[col]);
        bsum.y = __ldg(&ba[col + 1]) + __ldg(&bb_[col + 1]);
#pragma unroll
        for (int mt = 0; mt < 2; ++mt) {
#pragma unroll
            for (int h = 0; h < 2; ++h) {
                int row = row0 + m_base + mt * 16 + g + h * 8;
                if (row >= Nrows) continue;
                float sx = sigf(acc[mt][nt][2 * h]     + bsum.x);
                float sy = sigf(acc[mt][nt][2 * h + 1] + bsum.y);
                size_t p = (size_t)row * 64 + (col >> 1);
                if (mode == 0) {
                    reinterpret_cast<float2*>(g_z)[p] = make_float2(sx, sy);
                } else {
                    float2 xv = x2[p];
                    *reinterpret_cast<__half2*>(&g_rxh[(size_t)row * D + col]) =
                        __float22half2_rn(make_float2(sx * xv.x, sy * xv.y));
                }
            }
        }
    }
}

// Final gate, 64-ROW blocks: O = (1-z)*x + z*tanh(out@Wo1 + rx@Wo2 + b)
__global__ void __launch_bounds__(THREADS, 2)
gate2_mma_kernel(const __half* __restrict__ out_, const __half* __restrict__ rx_,
                 const __half* __restrict__ wh,
                 const float* __restrict__ bo1, const float* __restrict__ bo2,
                 float* __restrict__ O, int Nrows)
{
    __shared__ __half smA[2 * ABUF64_H];
    __shared__ __half smB[2 * BBUF_H];

    const __half* Wa = wh + (size_t)8 * D * D;
    const __half* Wb = wh + (size_t)9 * D * D;

    int tid  = threadIdx.x;
    int warp = tid >> 5;
    int lane = tid & 31;
    int g    = lane >> 2;
    int tig  = lane & 3;
    int m_base = (warp >> 2) * 32;   // 0,32
    int n_base = (warp & 3) * 32;    // 0..96
    int row0 = blockIdx.x * 64;

    float acc[2][4][4];
#pragma unroll
    for (int mt = 0; mt < 2; ++mt)
#pragma unroll
        for (int nt = 0; nt < 4; ++nt)
#pragma unroll
            for (int i = 0; i < 4; ++i) acc[mt][nt][i] = 0.f;

    dual_gemm_h64(out_, Wa, rx_, Wb, smA, smB, row0, Nrows, tid,
                  m_base, n_base, g, tig, acc);

    const float2* x2 = reinterpret_cast<const float2*>(g_x);
    const float2* z2 = reinterpret_cast<const float2*>(g_z);
#pragma unroll
    for (int nt = 0; nt < 4; ++nt) {
        int col = n_base + nt * 8 + 2 * tig;
        float2 bsum;
        bsum.x = __ldg(&bo1[col])     + __ldg(&bo2[col]);
        bsum.y = __ldg(&bo1[col + 1]) + __ldg(&bo2[col + 1]);
#pragma unroll
        for (int mt = 0; mt < 2; ++mt) {
#pragma unroll
            for (int h = 0; h < 2; ++h) {
                int row = row0 + m_base + mt * 16 + g + h * 8;
                if (row >= Nrows) continue;
                float tx = acc[mt][nt][2 * h]     + bsum.x;
                float ty = acc[mt][nt][2 * h + 1] + bsum.y;
                size_t p = (size_t)row * 64 + (col >> 1);
                float2 xv = x2[p];
                float2 zv = z2[p];
                float2 o;
                o.x = (1.f - zv.x) * xv.x + zv.x * tanhf(tx);
                o.y = (1.f - zv.y) * xv.y + zv.y * tanhf(ty);
                reinterpret_cast<float2*>(O)[p] = o;
            }
        }
    }
}

// ===========================================================================
// Conversions
// ===========================================================================
__global__ void cvtw_kernel(const float* w0, const float* w1, const float* w2,
                            const float* w3, const float* w4, const float* w5,
                            const float* w6, const float* w7, const float* w8,
                            const float* w9, __half* dst)
{
    const float* ws[10] = {w0, w1, w2, w3, w4, w5, w6, w7, w8, w9};
    const float* w = ws[blockIdx.y];
    int i = blockIdx.x * 256 + threadIdx.x;
    int n = i >> 7;
    int k = i & 127;
    dst[(size_t)blockIdx.y * D * D + i] = __float2half_rn(w[(size_t)k * D + n]);
}

__global__ void cvtx_kernel(const float* __restrict__ src, __half* __restrict__ dst, int n4)
{
    int i = blockIdx.x * blockDim.x + threadIdx.x;
    if (i < n4) {
        float4 v = reinterpret_cast<const float4*>(src)[i];
        __half2 h0 = __float22half2_rn(make_float2(v.x, v.y));
        __half2 h1 = __float22half2_rn(make_float2(v.z, v.w));
        reinterpret_cast<uint2*>(dst)[i] = make_uint2(
            *reinterpret_cast<uint32_t*>(&h0), *reinterpret_cast<uint32_t*>(&h1));
    }
}

// ===========================================================================
// CSR build + atomic-free aggregation
// ===========================================================================
__global__ void count_kernel(const int* __restrict__ rows, int E)
{
    int e = blockIdx.x * blockDim.x + threadIdx.x;
    if (e < E) atomicAdd(&g_cnt[rows[e]], 1);
}

__global__ void scan_kernel(int Nn)
{
    __shared__ int warp_tot[32];
    int t = threadIdx.x;
    int lane = t & 31, w = t >> 5;
    int C = (Nn + 1023) / 1024;
    int lo = t * C;
    int hi = min(lo + C, Nn);

    int sum = 0;
    for (int i = lo; i < hi; ++i) sum += g_cnt[i];

    int v = sum;
#pragma unroll
    for (int o = 1; o < 32; o <<= 1) {
        int u = __shfl_up_sync(0xffffffffu, v, o);
        if (lane >= o) v += u;
    }
    if (lane == 31) warp_tot[w] = v;
    __syncthreads();
    if (w == 0) {
        int tv = warp_tot[lane];
#pragma unroll
        for (int o = 1; o < 32; o <<= 1) {
            int u = __shfl_up_sync(0xffffffffu, tv, o);
            if (lane >= o) tv += u;
        }
        warp_tot[lane] = tv;
    }
    __syncthreads();
    int incl = v + (w > 0 ? warp_tot[w - 1] : 0);
    int run = incl - sum;

    for (int i = lo; i < hi; ++i) {
        int c = g_cnt[i];
        g_start[i] = run;
        g_cur[i] = run;
        run += c;
    }
    if (t == 1023) g_start[Nn] = run;
}

__global__ void fill_kernel(const int* __restrict__ rows, const int* __restrict__ cols,
                            const float* __restrict__ vals, int E)
{
    int e = blockIdx.x * blockDim.x + threadIdx.x;
    if (e < E) {
        int r = rows[e];
        int pos = atomicAdd(&g_cur[r], 1);
        g_edges[pos] = make_int2(cols[e], __float_as_int(vals[e]));
    }
}

// Warp per node; fp16 gather; 8 edges in flight (R12-proven); fp16 output.
__global__ void agg_kernel(const __half* __restrict__ xh, __half* __restrict__ aggh, int Nn)
{
    int gw = (blockIdx.x * blockDim.x + threadIdx.x) >> 5;
    int lane = threadIdx.x & 31;
    if (gw >= Nn) return;

    int s = __ldg(&g_start[gw]);
    int t = __ldg(&g_start[gw + 1]);
    const uint2* x2 = reinterpret_cast<const uint2*>(xh);

    float4 acc = make_float4(0.f, 0.f, 0.f, 0.f);
    int j = s;
    for (; j + 8 <= t; j += 8) {
        int2 ee[8];
        uint2 uu[8];
#pragma unroll
        for (int q = 0; q < 8; ++q) ee[q] = __ldg(&g_edges[j + q]);
#pragma unroll
        for (int q = 0; q < 8; ++q) uu[q] = x2[(size_t)ee[q].x * 32 + lane];
#pragma unroll
        for (int q = 0; q < 8; ++q) {
            float v = __int_as_float(ee[q].y);
            float2 a = __half22float2(*reinterpret_cast<__half2*>(&uu[q].x));
            float2 b = __half22float2(*reinterpret_cast<__half2*>(&uu[q].y));
            acc.x += v * a.x; acc.y += v * a.y; acc.z += v * b.x; acc.w += v * b.y;
        }
    }
    for (; j < t; ++j) {
        int2 ea = __ldg(&g_edges[j]);
        uint2 ua = x2[(size_t)ea.x * 32 + lane];
        float va = __int_as_float(ea.y);
        float2 a = __half22float2(*reinterpret_cast<__half2*>(&ua.x));
        float2 b = __half22float2(*reinterpret_cast<__half2*>(&ua.y));
        acc.x += va * a.x; acc.y += va * a.y; acc.z += va * b.x; acc.w += va * b.y;
    }
    __half2 h0 = __float22half2_rn(make_float2(acc.x, acc.y));
    __half2 h1 = __float22half2_rn(make_float2(acc.z, acc.w));
    reinterpret_cast<uint2*>(aggh)[(size_t)gw * 32 + lane] = make_uint2(
        *reinterpret_cast<uint32_t*>(&h0), *reinterpret_cast<uint32_t*>(&h1));
}

// ---------------------------------------------------------------------------
extern "C" void kernel_launch(void* const* d_in, const int* in_sizes, int n_in,
                              void* d_out, int out_size)
{
    const float* x_in  = (const float*)d_in[0];
    const int*   rows  = (const int*)  d_in[1];
    const int*   cols  = (const int*)  d_in[2];
    const float* vals  = (const float*)d_in[3];
    const float* m1_W1 = (const float*)d_in[4];
    const float* m1_b1 = (const float*)d_in[5];
    const float* m1_W2 = (const float*)d_in[6];
    const float* m1_b2 = (const float*)d_in[7];
    const float* m2_W1 = (const float*)d_in[8];
    const float* m2_b1 = (const float*)d_in[9];
    const float* m2_W2 = (const float*)d_in[10];
    const float* m2_b2 = (const float*)d_in[11];
    const float* Wu1   = (const float*)d_in[12];
    const float* bu1   = (const float*)d_in[13];
    const float* Wu2   = (const float*)d_in[14];
    const float* bu2   = (const float*)d_in[15];
    const float* Wr1   = (const float*)d_in[16];
    const float* br1   = (const float*)d_in[17];
    const float* Wr2   = (const float*)d_in[18];
    const float* br2   = (const float*)d_in[19];
    const float* Wo1   = (const float*)d_in[20];
    const float* bo1   = (const float*)d_in[21];
    const float* Wo2   = (const float*)d_in[22];
    const float* bo2   = (const float*)d_in[23];

    int N = in_sizes[0] / D;
    int E = in_sizes[1];

    float *px;
    __half *pxh, *pxinh, *paggh, *pouth, *prxh, *pwh;
    int* pcnt;
    cudaGetSymbolAddress((void**)&px,    g_x);
    cudaGetSymbolAddress((void**)&pxh,   g_xh);
    cudaGetSymbolAddress((void**)&pxinh, g_xinh);
    cudaGetSymbolAddress((void**)&paggh, g_aggh);
    cudaGetSymbolAddress((void**)&pouth, g_outh);
    cudaGetSymbolAddress((void**)&prxh,  g_rxh);
    cudaGetSymbolAddress((void**)&pwh,   g_wh);
    cudaGetSymbolAddress((void**)&pcnt,  g_cnt);

    static cudaStream_t s_side = nullptr;
    static cudaEvent_t ev_fork = nullptr, ev_join = nullptr;
    if (!s_side) {
        cudaStreamCreateWithFlags(&s_side, cudaStreamNonBlocking);
        cudaEventCreateWithFlags(&ev_fork, cudaEventDisableTiming);
        cudaEventCreateWithFlags(&ev_join, cudaEventDisableTiming);
    }

    int smem_mlp = (2 * ABUF64_H + 2 * BBUF_H + 64 * SHH) * (int)sizeof(__half);  // 72704 B
    cudaFuncSetAttribute(mlp2_mma_kernel<true>,  cudaFuncAttributeMaxDynamicSharedMemorySize, smem_mlp);
    cudaFuncSetAttribute(mlp2_mma_kernel<false>, cudaFuncAttributeMaxDynamicSharedMemorySize, smem_mlp);

    int nblk128 = (N + 127) / 128;  // 391
    int nblk64  = (N + 63) / 64;    // 782
    int eblk = (E + 255) / 256;
    int n4 = N * D / 4;

    // ---- fork: CSR build on side stream ----
    cudaEventRecord(ev_fork, 0);
    cudaStreamWaitEvent(s_side, ev_fork, 0);
    cudaMemsetAsync(pcnt, 0, (size_t)N * sizeof(int), s_side);
    count_kernel<<<eblk, 256, 0, s_side>>>(rows, E);
    scan_kernel<<<1, 1024, 0, s_side>>>(N);
    fill_kernel<<<eblk, 256, 0, s_side>>>(rows, cols, vals, E);
    cudaEventRecord(ev_join, s_side);

    // ---- main: conversions, then pipeline ----
    dim3 wgrid(64, 10);
    cvtw_kernel<<<wgrid, 256>>>(m1_W1, m1_W2, m2_W1, m2_W2, Wu1, Wu2, Wr1, Wr2, Wo1, Wo2, pwh);
    cvtx_kernel<<<(n4 + 255) / 256, 256>>>(x_in, pxinh, n4);

    mlp2_mma_kernel<true><<<nblk64, THREADS, smem_mlp>>>(
        pxinh, pwh + 0 * D * D, m1_b1, pwh + 1 * D * D, m1_b2, px, pxh, N);

    cudaStreamWaitEvent(0, ev_join, 0);
    agg_kernel<<<(N * 32 + 255) / 256, 256>>>(pxh, paggh, N);

    mlp2_mma_kernel<false><<<nblk64, THREADS, smem_mlp>>>(
        paggh, pwh + 2 * D * D, m2_b1, pwh + 3 * D * D, m2_b2, nullptr, pouth, N);

    dim3 grid01(nblk128, 2);
    gate01_mma_kernel<<<grid01, THREADS>>>(pouth, pxh, pwh, bu1, bu2, br1, br2, N);
    gate2_mma_kernel<<<nblk64, THREADS>>>(pouth, prxh, pwh, bo1, bo2, (float*)d_out, N);
}